// round 8
// baseline (speedup 1.0000x reference)
#include <cuda_runtime.h>
#include <cooperative_groups.h>
#include <cstdint>

namespace cg = cooperative_groups;

#define N_NODES 100000
#define N_EDGES 3200000
#define BLOCK   1024

// Scratch (static device globals — no allocation allowed).
// g_acc is zero at module load and self-reset by the node phase each call,
// so no init pass is needed and every invocation sees zeros (deterministic).
__device__ float2 g_acc[N_NODES];   // .x = denom, .y = numer
__device__ float  g_inv[N_NODES];   // dense reciprocal for the normalize phase

__device__ __forceinline__ void red_add_v2(float2* addr, float a, float b) {
    asm volatile("red.global.add.v2.f32 [%0], {%1, %2};"
                 :: "l"(addr), "f"(a), "f"(b) : "memory");
}

// One cooperative kernel, three phases separated by grid.sync():
//  P1 edges: pair_pred -> pp (global), ex -> SMEM, red.v2 into g_acc[dst]
//  P2 nodes: out = W0*numer/denom, g_inv = 1/denom, reset g_acc for next call
//  P3 attn:  attn[e] = ex(SMEM) * g_inv[dst(SMEM)]   (no global re-reads)
__global__ void __launch_bounds__(BLOCK, 1) fused_kernel(
    const float* __restrict__ x,
    const int*   __restrict__ ei,
    const float* __restrict__ ea,
    const float* __restrict__ W,
    const float* __restrict__ Wn,
    const float* __restrict__ We,
    float* __restrict__ out,
    float* __restrict__ attn,
    float* __restrict__ pp,
    int ept)
{
    extern __shared__ float2 s_ed[];          // [BLOCK * ept] : (ex, dst bits)
    __shared__ float sWe[32];
    __shared__ float sWn[4];

    int t = threadIdx.x;
    if (t < 32)      sWe[t]      = We[t];
    else if (t < 36) sWn[t - 32] = Wn[t - 32];
    __syncthreads();

    cg::grid_group grid = cg::this_grid();

    size_t base = (size_t)blockIdx.x * BLOCK * ept;

    // ---- Phase 1: edges ----
    for (int k = 0; k < ept; k++) {
        size_t e = base + (size_t)k * BLOCK + t;
        float ex = 0.0f;
        int dst = 0;
        if (e < N_EDGES) {
            int src = ei[e];
            dst = ei[N_EDGES + e];
            float xs = __ldg(x + src);
            float xd = __ldg(x + dst);

            const float4* ea4 = (const float4*)(ea + e * 16);
            float4 v0 = __ldcs(ea4 + 0);
            float4 v1 = __ldcs(ea4 + 1);
            float4 v2 = __ldcs(ea4 + 2);
            float4 v3 = __ldcs(ea4 + 3);

            float p0 = xs * sWn[0] + xd * sWn[2];
            float p1 = xs * sWn[1] + xd * sWn[3];

            p0 += v0.x * sWe[0]  + v0.y * sWe[2]  + v0.z * sWe[4]  + v0.w * sWe[6];
            p1 += v0.x * sWe[1]  + v0.y * sWe[3]  + v0.z * sWe[5]  + v0.w * sWe[7];
            p0 += v1.x * sWe[8]  + v1.y * sWe[10] + v1.z * sWe[12] + v1.w * sWe[14];
            p1 += v1.x * sWe[9]  + v1.y * sWe[11] + v1.z * sWe[13] + v1.w * sWe[15];
            p0 += v2.x * sWe[16] + v2.y * sWe[18] + v2.z * sWe[20] + v2.w * sWe[22];
            p1 += v2.x * sWe[17] + v2.y * sWe[19] + v2.z * sWe[21] + v2.w * sWe[23];
            p0 += v3.x * sWe[24] + v3.y * sWe[26] + v3.z * sWe[28] + v3.w * sWe[30];
            p1 += v3.x * sWe[25] + v3.y * sWe[27] + v3.z * sWe[29] + v3.w * sWe[31];

            // leaky_relu(., 0.2)
            p0 = (p0 > 0.0f) ? p0 : 0.2f * p0;
            p1 = (p1 > 0.0f) ? p1 : 0.2f * p1;

            __stcs((float2*)pp + e, make_float2(p0, p1));   // pure output stream

            ex = __expf(p0 - p1);   // softmax shift-invariant; |score| << 88
            red_add_v2(&g_acc[dst], ex, ex * xs);
        }
        s_ed[k * BLOCK + t] = make_float2(ex, __int_as_float(dst));
    }

    grid.sync();

    // ---- Phase 2: nodes (also reset g_acc for the next invocation) ----
    int gsz = gridDim.x * BLOCK;
    for (int i = blockIdx.x * BLOCK + t; i < N_NODES; i += gsz) {
        float2 a = g_acc[i];
        float inv = 1.0f / (a.x + 1e-16f);
        out[i] = W[0] * a.y * inv;
        g_inv[i] = inv;
        g_acc[i] = make_float2(0.0f, 0.0f);
    }

    grid.sync();

    // ---- Phase 3: normalize from SMEM-resident (ex, dst) ----
    for (int k = 0; k < ept; k++) {
        size_t e = base + (size_t)k * BLOCK + t;
        if (e < N_EDGES) {
            float2 s = s_ed[k * BLOCK + t];
            int dst = __float_as_int(s.y);
            __stcs(attn + e, s.x * __ldg(g_inv + dst));
        }
    }
}

extern "C" void kernel_launch(void* const* d_in, const int* in_sizes, int n_in,
                              void* d_out, int out_size)
{
    // Resolve inputs by element count (all distinct) — robust to ordering.
    const float* x  = nullptr;   // 100000
    const int*   ei = nullptr;   // 6400000 (int32)
    const float* ea = nullptr;   // 51200000
    const float* W  = nullptr;   // 1
    const float* Wn = nullptr;   // 4
    const float* We = nullptr;   // 32
    for (int i = 0; i < n_in; i++) {
        switch (in_sizes[i]) {
            case N_NODES:      x  = (const float*)d_in[i]; break;
            case 2 * N_EDGES:  ei = (const int*)d_in[i];   break;
            case 16 * N_EDGES: ea = (const float*)d_in[i]; break;
            case 1:            W  = (const float*)d_in[i]; break;
            case 4:            Wn = (const float*)d_in[i]; break;
            case 32:           We = (const float*)d_in[i]; break;
        }
    }

    float* out  = (float*)d_out;                 // [N]
    float* attn = out + N_NODES;                 // [E]
    float* pp   = out + N_NODES + N_EDGES;       // [E,2]

    int dev = 0;
    cudaGetDevice(&dev);
    int sms = 0;
    cudaDeviceGetAttribute(&sms, cudaDevAttrMultiProcessorCount, dev);

    long long threads_total = (long long)sms * BLOCK;
    int ept = (int)((N_EDGES + threads_total - 1) / threads_total);
    size_t shmem = (size_t)BLOCK * ept * sizeof(float2);

    cudaFuncSetAttribute(fused_kernel,
                         cudaFuncAttributeMaxDynamicSharedMemorySize, (int)shmem);

    void* args[] = { (void*)&x, (void*)&ei, (void*)&ea, (void*)&W, (void*)&Wn,
                     (void*)&We, (void*)&out, (void*)&attn, (void*)&pp, (void*)&ept };
    cudaLaunchCooperativeKernel((void*)fused_kernel,
                                dim3(sms), dim3(BLOCK), args, shmem, 0);
}

// round 9
// speedup vs baseline: 1.1477x; 1.1477x over previous
#include <cuda_runtime.h>
#include <cstdint>

#define N_NODES 100000
#define N_EDGES 3200000
#define S_NODES 51200   // 200KB of g_inv cached in smem for the attn pass

// Scratch (static device globals — no allocation allowed).
// g_acc zero at module load; node_kernel self-resets it after reading, so
// every invocation (correctness run + each graph replay) sees zeros.
__device__ float2 g_acc[N_NODES];   // .x = denom, .y = numer
__device__ float  g_inv[N_NODES];   // dense reciprocal for the normalize pass

__device__ __forceinline__ void red_add_v2(float2* addr, float a, float b) {
    asm volatile("red.global.add.v2.f32 [%0], {%1, %2};"
                 :: "l"(addr), "f"(a), "f"(b) : "memory");
}

// Edge pass, 1 edge/thread (R7-proven shape):
//  - pair_pred = leaky_relu([x_src, x_dst] @ Wn + ea @ We, 0.2) -> pp
//  - g_acc[dst] += (ex, ex * x[src])  via one red.v2; ex not stored.
__global__ void __launch_bounds__(256) edge_kernel(
                            const float* __restrict__ x,
                            const int*   __restrict__ ei,
                            const float* __restrict__ ea,
                            const float* __restrict__ Wn,
                            const float* __restrict__ We,
                            float* __restrict__ pp_out)
{
    __shared__ float sWe[32];
    __shared__ float sWn[4];
    int t = threadIdx.x;
    if (t < 32)       sWe[t]      = We[t];
    else if (t < 36)  sWn[t - 32] = Wn[t - 32];
    __syncthreads();

    int e = blockIdx.x * blockDim.x + t;
    if (e >= N_EDGES) return;

    int src = ei[e];
    int dst = ei[N_EDGES + e];
    float xs = __ldg(x + src);
    float xd = __ldg(x + dst);

    // edge_attr is a pure stream — evict-first so it doesn't pollute L2.
    const float4* ea4 = (const float4*)(ea + (size_t)e * 16);
    float4 v0 = __ldcs(ea4 + 0);
    float4 v1 = __ldcs(ea4 + 1);
    float4 v2 = __ldcs(ea4 + 2);
    float4 v3 = __ldcs(ea4 + 3);

    float p0 = xs * sWn[0] + xd * sWn[2];
    float p1 = xs * sWn[1] + xd * sWn[3];

    p0 += v0.x * sWe[0]  + v0.y * sWe[2]  + v0.z * sWe[4]  + v0.w * sWe[6];
    p1 += v0.x * sWe[1]  + v0.y * sWe[3]  + v0.z * sWe[5]  + v0.w * sWe[7];
    p0 += v1.x * sWe[8]  + v1.y * sWe[10] + v1.z * sWe[12] + v1.w * sWe[14];
    p1 += v1.x * sWe[9]  + v1.y * sWe[11] + v1.z * sWe[13] + v1.w * sWe[15];
    p0 += v2.x * sWe[16] + v2.y * sWe[18] + v2.z * sWe[20] + v2.w * sWe[22];
    p1 += v2.x * sWe[17] + v2.y * sWe[19] + v2.z * sWe[21] + v2.w * sWe[23];
    p0 += v3.x * sWe[24] + v3.y * sWe[26] + v3.z * sWe[28] + v3.w * sWe[30];
    p1 += v3.x * sWe[25] + v3.y * sWe[27] + v3.z * sWe[29] + v3.w * sWe[31];

    // leaky_relu(., 0.2)
    p0 = (p0 > 0.0f) ? p0 : 0.2f * p0;
    p1 = (p1 > 0.0f) ? p1 : 0.2f * p1;

    ((float2*)pp_out)[e] = make_float2(p0, p1);

    float ex = __expf(p0 - p1);   // softmax shift-invariant; |score| << 88
    red_add_v2(&g_acc[dst], ex, ex * xs);
}

// out[i] = W0 * numer * inv_denom ; stash inv_denom; reset g_acc for next call.
__global__ void node_kernel(float* __restrict__ out, const float* __restrict__ W) {
    int i = blockIdx.x * blockDim.x + threadIdx.x;
    if (i < N_NODES) {
        float2 a = g_acc[i];
        float inv = 1.0f / (a.x + 1e-16f);
        out[i] = W[0] * a.y * inv;
        g_inv[i] = inv;
        g_acc[i] = make_float2(0.0f, 0.0f);
    }
}

// Normalize pass: hybrid gather. First 51200 g_inv entries live in SMEM
// (LDS pipe — no L1tex wavefronts); the rest go through LDG. ~51% of the
// 12.8M random gather wavefronts are eliminated.
__global__ void __launch_bounds__(1024, 1) attn_kernel(
                            const int*   __restrict__ ei,
                            const float* __restrict__ pp,
                            float* __restrict__ attn)
{
    extern __shared__ float s_inv[];

    int t = threadIdx.x;
    // Cooperative vectorized fill: 51200 floats = 12800 float4.
    const float4* g4 = (const float4*)g_inv;
    float4*       s4 = (float4*)s_inv;
    for (int i = t; i < S_NODES / 4; i += 1024) s4[i] = g4[i];
    __syncthreads();

    int stride = gridDim.x * 1024 * 4;
    for (int e = (blockIdx.x * 1024 + t) * 4; e < N_EDGES; e += stride) {
        int4 d = *(const int4*)(ei + N_EDGES + e);

        float i0 = (d.x < S_NODES) ? s_inv[d.x] : __ldg(g_inv + d.x);
        float i1 = (d.y < S_NODES) ? s_inv[d.y] : __ldg(g_inv + d.y);
        float i2 = (d.z < S_NODES) ? s_inv[d.z] : __ldg(g_inv + d.z);
        float i3 = (d.w < S_NODES) ? s_inv[d.w] : __ldg(g_inv + d.w);

        float4 pa = __ldcs((const float4*)(pp + 2 * (size_t)e));
        float4 pb = __ldcs((const float4*)(pp + 2 * (size_t)e + 4));

        float ex0 = __expf(pa.x - pa.y);
        float ex1 = __expf(pa.z - pa.w);
        float ex2 = __expf(pb.x - pb.y);
        float ex3 = __expf(pb.z - pb.w);

        __stcs((float4*)(attn + e),
               make_float4(ex0 * i0, ex1 * i1, ex2 * i2, ex3 * i3));
    }
}

extern "C" void kernel_launch(void* const* d_in, const int* in_sizes, int n_in,
                              void* d_out, int out_size)
{
    // Resolve inputs by element count (all distinct) — robust to ordering.
    const float* x  = nullptr;   // 100000
    const int*   ei = nullptr;   // 6400000 (int32)
    const float* ea = nullptr;   // 51200000
    const float* W  = nullptr;   // 1
    const float* Wn = nullptr;   // 4
    const float* We = nullptr;   // 32
    for (int i = 0; i < n_in; i++) {
        switch (in_sizes[i]) {
            case N_NODES:      x  = (const float*)d_in[i]; break;
            case 2 * N_EDGES:  ei = (const int*)d_in[i];   break;
            case 16 * N_EDGES: ea = (const float*)d_in[i]; break;
            case 1:            W  = (const float*)d_in[i]; break;
            case 4:            Wn = (const float*)d_in[i]; break;
            case 32:           We = (const float*)d_in[i]; break;
        }
    }

    float* out  = (float*)d_out;                 // [N]
    float* attn = out + N_NODES;                 // [E]
    float* pp   = out + N_NODES + N_EDGES;       // [E,2]

    int dev = 0;
    cudaGetDevice(&dev);
    int sms = 0;
    cudaDeviceGetAttribute(&sms, cudaDevAttrMultiProcessorCount, dev);

    size_t shmem = (size_t)S_NODES * sizeof(float);   // 200KB
    static bool attr_set = false;
    if (!attr_set) {
        cudaFuncSetAttribute(attn_kernel,
                             cudaFuncAttributeMaxDynamicSharedMemorySize, (int)shmem);
        attr_set = true;
    }

    edge_kernel<<<(N_EDGES + 255) / 256, 256>>>(x, ei, ea, Wn, We, pp);
    node_kernel<<<(N_NODES + 255) / 256, 256>>>(out, W);
    attn_kernel<<<sms, 1024, shmem>>>(ei, pp, attn);
}

// round 10
// speedup vs baseline: 1.3238x; 1.1534x over previous
#include <cuda_runtime.h>
#include <cstdint>

#define N_NODES 100000
#define N_EDGES 3200000

// Scratch (static device globals — no allocation allowed).
// g_acc is zero at module load; node_kernel self-resets it after reading, so
// every invocation (correctness run + each graph replay) sees zeros.
__device__ float2 g_acc[N_NODES];   // .x = denom, .y = numer
__device__ float  g_inv[N_NODES];   // dense reciprocal for the normalize pass

__device__ __forceinline__ void red_add_v2(float2* addr, float a, float b) {
    asm volatile("red.global.add.v2.f32 [%0], {%1, %2};"
                 :: "l"(addr), "f"(a), "f"(b) : "memory");
}

// Edge pass, 1 edge/thread (proven shape):
//  - pair_pred = leaky_relu([x_src, x_dst] @ Wn + ea @ We, 0.2) -> pp
//  - g_acc[dst] += (ex, ex * x[src])  via one red.v2; ex not stored.
__global__ void __launch_bounds__(256) edge_kernel(
                            const float* __restrict__ x,
                            const int*   __restrict__ ei,
                            const float* __restrict__ ea,
                            const float* __restrict__ Wn,
                            const float* __restrict__ We,
                            float* __restrict__ pp_out)
{
    __shared__ float sWe[32];
    __shared__ float sWn[4];
    int t = threadIdx.x;
    if (t < 32)       sWe[t]      = We[t];
    else if (t < 36)  sWn[t - 32] = Wn[t - 32];
    __syncthreads();

    int e = blockIdx.x * blockDim.x + t;
    if (e >= N_EDGES) return;

    int src = ei[e];
    int dst = ei[N_EDGES + e];
    float xs = __ldg(x + src);
    float xd = __ldg(x + dst);

    // edge_attr is a pure stream — evict-first so it doesn't pollute L1/L2.
    const float4* ea4 = (const float4*)(ea + (size_t)e * 16);
    float4 v0 = __ldcs(ea4 + 0);
    float4 v1 = __ldcs(ea4 + 1);
    float4 v2 = __ldcs(ea4 + 2);
    float4 v3 = __ldcs(ea4 + 3);

    float p0 = xs * sWn[0] + xd * sWn[2];
    float p1 = xs * sWn[1] + xd * sWn[3];

    p0 += v0.x * sWe[0]  + v0.y * sWe[2]  + v0.z * sWe[4]  + v0.w * sWe[6];
    p1 += v0.x * sWe[1]  + v0.y * sWe[3]  + v0.z * sWe[5]  + v0.w * sWe[7];
    p0 += v1.x * sWe[8]  + v1.y * sWe[10] + v1.z * sWe[12] + v1.w * sWe[14];
    p1 += v1.x * sWe[9]  + v1.y * sWe[11] + v1.z * sWe[13] + v1.w * sWe[15];
    p0 += v2.x * sWe[16] + v2.y * sWe[18] + v2.z * sWe[20] + v2.w * sWe[22];
    p1 += v2.x * sWe[17] + v2.y * sWe[19] + v2.z * sWe[21] + v2.w * sWe[23];
    p0 += v3.x * sWe[24] + v3.y * sWe[26] + v3.z * sWe[28] + v3.w * sWe[30];
    p1 += v3.x * sWe[25] + v3.y * sWe[27] + v3.z * sWe[29] + v3.w * sWe[31];

    // leaky_relu(., 0.2)
    p0 = (p0 > 0.0f) ? p0 : 0.2f * p0;
    p1 = (p1 > 0.0f) ? p1 : 0.2f * p1;

    ((float2*)pp_out)[e] = make_float2(p0, p1);   // default policy: L2-resident for attn pass

    float ex = __expf(p0 - p1);   // softmax shift-invariant; |score| << 88
    red_add_v2(&g_acc[dst], ex, ex * xs);
}

// out[i] = W0 * numer * inv_denom ; stash inv_denom; reset g_acc for next call.
__global__ void node_kernel(float* __restrict__ out, const float* __restrict__ W) {
    int i = blockIdx.x * blockDim.x + threadIdx.x;
    if (i < N_NODES) {
        float2 a = g_acc[i];
        float inv = 1.0f / (a.x + 1e-16f);
        out[i] = W[0] * a.y * inv;
        g_inv[i] = inv;
        g_acc[i] = make_float2(0.0f, 0.0f);
    }
}

// Normalize pass, 4 edges/thread (R7-proven shape): re-read pair_pred,
// recompute ex, gather dense g_inv, write attn once (streaming).
__global__ void __launch_bounds__(256) attn_kernel(
                            const int*   __restrict__ ei,
                            const float* __restrict__ pp,
                            float* __restrict__ attn)
{
    int e = (blockIdx.x * blockDim.x + threadIdx.x) * 4;
    if (e >= N_EDGES) return;

    int4 d = *(const int4*)(ei + N_EDGES + e);

    // Issue the 4 random gathers early (longest latency).
    float i0 = __ldg(g_inv + d.x);
    float i1 = __ldg(g_inv + d.y);
    float i2 = __ldg(g_inv + d.z);
    float i3 = __ldg(g_inv + d.w);

    float4 pa = *(const float4*)(pp + 2 * (size_t)e);      // edges e, e+1
    float4 pb = *(const float4*)(pp + 2 * (size_t)e + 4);  // edges e+2, e+3

    float ex0 = __expf(pa.x - pa.y);
    float ex1 = __expf(pa.z - pa.w);
    float ex2 = __expf(pb.x - pb.y);
    float ex3 = __expf(pb.z - pb.w);

    __stcs((float4*)(attn + e),
           make_float4(ex0 * i0, ex1 * i1, ex2 * i2, ex3 * i3));
}

extern "C" void kernel_launch(void* const* d_in, const int* in_sizes, int n_in,
                              void* d_out, int out_size)
{
    // Resolve inputs by element count (all distinct) — robust to ordering.
    const float* x  = nullptr;   // 100000
    const int*   ei = nullptr;   // 6400000 (int32)
    const float* ea = nullptr;   // 51200000
    const float* W  = nullptr;   // 1
    const float* Wn = nullptr;   // 4
    const float* We = nullptr;   // 32
    for (int i = 0; i < n_in; i++) {
        switch (in_sizes[i]) {
            case N_NODES:      x  = (const float*)d_in[i]; break;
            case 2 * N_EDGES:  ei = (const int*)d_in[i];   break;
            case 16 * N_EDGES: ea = (const float*)d_in[i]; break;
            case 1:            W  = (const float*)d_in[i]; break;
            case 4:            Wn = (const float*)d_in[i]; break;
            case 32:           We = (const float*)d_in[i]; break;
        }
    }

    float* out  = (float*)d_out;                 // [N]
    float* attn = out + N_NODES;                 // [E]
    float* pp   = out + N_NODES + N_EDGES;       // [E,2]

    edge_kernel<<<(N_EDGES + 255) / 256, 256>>>(x, ei, ea, Wn, We, pp);
    node_kernel<<<(N_NODES + 255) / 256, 256>>>(out, W);
    attn_kernel<<<N_EDGES / (256 * 4), 256>>>(ei, pp, attn);
}